// round 10
// baseline (speedup 1.0000x reference)
#include <cuda_runtime.h>
#include <stdint.h>
#include <math.h>

// Problem constants (fixed by the dataset problem)
#define KST   4096   // number of states
#define NSEQ  8192   // number of sequences
#define SLEN  1024   // sequence length

// Scratch (allocation-free rule: __device__ globals)
__device__ float g_log_init[KST];
__device__ float g_log_trans[(size_t)KST * KST];   // 64 MB, L2-resident
__device__ uint2 g_step_keys[SLEN];
__device__ unsigned int g_rowmax_bits;             // float bits of max(log) (<0)

// ---------------------------------------------------------------------------
// Threefry-2x32 (20 rounds) — host/prep version
// ---------------------------------------------------------------------------
__host__ __device__ __forceinline__ uint32_t rotl32(uint32_t x, int r) {
#ifdef __CUDA_ARCH__
    return __funnelshift_l(x, x, r);
#else
    return (x << r) | (x >> (32 - r));
#endif
}

__host__ __device__ __forceinline__ void threefry2x32(
    uint32_t k0, uint32_t k1, uint32_t x0, uint32_t x1,
    uint32_t* o0, uint32_t* o1)
{
    const uint32_t k2 = k0 ^ k1 ^ 0x1BD11BDAu;
    x0 += k0; x1 += k1;
#define TF_R(r) { x0 += x1; x1 = rotl32(x1, (r)); x1 ^= x0; }
    TF_R(13) TF_R(15) TF_R(26) TF_R(6)
    x0 += k1; x1 += k2 + 1u;
    TF_R(17) TF_R(29) TF_R(16) TF_R(24)
    x0 += k2; x1 += k0 + 2u;
    TF_R(13) TF_R(15) TF_R(26) TF_R(6)
    x0 += k0; x1 += k1 + 3u;
    TF_R(17) TF_R(29) TF_R(16) TF_R(24)
    x0 += k1; x1 += k2 + 4u;
    TF_R(13) TF_R(15) TF_R(26) TF_R(6)
    x0 += k2; x1 += k0 + 5u;
#undef TF_R
    *o0 = x0; *o1 = x1;
}

// ---------------------------------------------------------------------------
__global__ void reset_kernel() { g_rowmax_bits = 0xFFFFFFFFu; }

// ---------------------------------------------------------------------------
// Prep: logs, step keys, and global max-log (for the pruning threshold).
// All logs are < 0, so float-max == uint-bits-min -> atomicMin on bits.
// ---------------------------------------------------------------------------
__global__ void prep_kernel(const float* __restrict__ init_p,
                            const float* __restrict__ trans_p,
                            uint32_t key0x, uint32_t key0y,
                            uint32_t kloopx, uint32_t kloopy)
{
    __shared__ float sred[256];
    const long long idx    = (long long)blockIdx.x * blockDim.x + threadIdx.x;
    const long long stride = (long long)gridDim.x * blockDim.x;
    const long long total  = (long long)KST * KST;

    float lmax = -INFINITY;
    for (long long i = idx; i < total; i += stride) {
        const float l = logf(trans_p[i]);
        g_log_trans[i] = l;
        lmax = fmaxf(lmax, l);
    }
    if (idx < KST) {
        const float l = logf(init_p[idx]);
        g_log_init[idx] = l;
        lmax = fmaxf(lmax, l);
    }
    if (idx < SLEN) {
        if (idx == 0) {
            g_step_keys[0] = make_uint2(key0x, key0y);
        } else {
            uint32_t o0, o1;
            threefry2x32(kloopx, kloopy, 0u, (uint32_t)idx, &o0, &o1);
            g_step_keys[idx] = make_uint2(o0, o1);
        }
    }
    sred[threadIdx.x] = lmax;
    __syncthreads();
    for (int o = 128; o > 0; o >>= 1) {
        if (threadIdx.x < o)
            sred[threadIdx.x] = fmaxf(sred[threadIdx.x], sred[threadIdx.x + o]);
        __syncthreads();
    }
    if (threadIdx.x == 0)
        atomicMin(&g_rowmax_bits, __float_as_uint(sred[0]));
}

// ---------------------------------------------------------------------------
// Conservative bits-threshold from a mapped achieved best value.
// u_thr = exp(-exp(-(vb - R))), heavily under-padded so every skipped
// element is PROVABLY strictly below vb -> argmax unchanged bit-for-bit.
// ---------------------------------------------------------------------------
__device__ __forceinline__ uint32_t thr_from_mapped(unsigned m, float R)
{
    const unsigned ub = (m & 0x80000000u) ? (m & 0x7FFFFFFFu) : ~m;  // unmap
    const float vb = __uint_as_float(ub);
    const float t  = vb - R;
    const float w  = expf(-t);
    const float up = expf(-w) * 0.99998f;                  // >=10x composed err
    uint32_t nt = 0u;
    if (up >= 1.0f) {
        nt = 0xFFFFFFFFu;
    } else if (up > 0.0f) {
        const unsigned mant = __float_as_uint(1.0f + up) & 0x7FFFFFu;
        nt = (mant > 8u) ? ((mant - 8u) << 9) : 0u;        // extra ulp pad
    }
    return nt;   // NaN / nonpositive -> 0 (compute everything)
}

// gumbel value -> order-preserving unsigned map
__device__ __forceinline__ unsigned map_float(float v)
{
    const unsigned ub = __float_as_uint(v);
    return (ub & 0x80000000u) ? ~ub : (ub | 0x80000000u);
}

// ---------------------------------------------------------------------------
// Main sampler.
//  - All-SHF threefry (R9's IMAD-rot regressed: +issue slots > -ALU slots).
//  - TWO interleaved independent threefry chains per thread per iteration
//    (elements k and k+256): 2x ILP on the serial 20-round chain, and per-
//    batch overhead (threshold LDS, vote, loop) amortized over 2 elements.
//  - Rare branch: per-thread best-of-2 as 64-bit pack
//        (mapped_value << 32) | (0x7FFFFFFF - index)
//    (value-major, ties -> smaller index == XLA first-max), u64 butterfly
//    max across the warp, single atomicMax into the block-shared pack.
//    Identical selection semantics to the per-batch REDUX version.
//  - ONE __syncthreads per step (3-buffer rotation for race-free reset).
// Output written as float32 (harness output dtype).
// ---------------------------------------------------------------------------
__global__ void __launch_bounds__(256)
sample_kernel(float* __restrict__ out, uint32_t one)
{
    const int n    = blockIdx.x;
    const int tid  = threadIdx.x;

    __shared__ unsigned long long s_pack[3];
    if (tid == 0) { s_pack[0] = 0ull; s_pack[1] = 0ull; s_pack[2] = 0ull; }
    __syncthreads();

    const uint32_t ebase  = (uint32_t)n * (uint32_t)KST;
    const float    TINY32 = 1.17549435e-38f;            // finfo(f32).tiny
    const float    R      = __uint_as_float(g_rowmax_bits);

    int prev = 0;  // unused at s=0 (uses log_init)

    for (int s = 0; s < SLEN; ++s) {
        const uint2 key = g_step_keys[s];
        const float* __restrict__ row =
            (s == 0) ? g_log_init : (g_log_trans + (size_t)prev * KST);

        const int bsel = s - (s / 3) * 3;               // s % 3
        unsigned long long* pk = &s_pack[bsel];
        const uint32_t pk_sa = (uint32_t)__cvta_generic_to_shared(pk);

        // hoisted key-injection constants
        const uint32_t k0 = key.x, k1 = key.y, kx = k0 ^ k1 ^ 0x1BD11BDAu;
        const uint32_t i1b = kx + 1u, i2b = k0 + 2u, i3b = k1 + 3u,
                       i4b = kx + 4u, i5b = k0 + 5u;
        const uint32_t x1baseA = k1 + ebase + (uint32_t)tid;
        const uint32_t x1baseB = x1baseA + 256u;

        unsigned last_sb = 0u;   // cached block-best (mapped); 0 < any real
        uint32_t bthr    = 0u;   // candidate iff bits >= bthr

#pragma unroll 2
        for (int j = 0; j < KST / 512; ++j) {           // 8 pair-iterations
            const uint32_t c0 = (uint32_t)(j * 512);
            // two interleaved chains: elements kA = tid+j*512, kB = kA+256
            uint32_t a0 = k0, a1 = one * c0 + x1baseA;
            uint32_t b0 = k0, b1 = one * c0 + x1baseB;
#define TFR2(r) { a0 = one * a0 + a1;  b0 = one * b0 + b1;                    \
                  a1 = __funnelshift_l(a1, a1, (r)) ^ a0;                     \
                  b1 = __funnelshift_l(b1, b1, (r)) ^ b0; }
#define INJ2(p, q) { a0 = one * a0 + (p); a1 = one * a1 + (q);                \
                     b0 = one * b0 + (p); b1 = one * b1 + (q); }
            TFR2(13) TFR2(15) TFR2(26) TFR2(6)
            INJ2(k1, i1b)
            TFR2(17) TFR2(29) TFR2(16) TFR2(24)
            INJ2(kx, i2b)
            TFR2(13) TFR2(15) TFR2(26) TFR2(6)
            INJ2(k0, i3b)
            TFR2(17) TFR2(29) TFR2(16) TFR2(24)
            INJ2(k1, i4b)
            TFR2(13) TFR2(15) TFR2(26) TFR2(6)
            INJ2(kx, i5b)
#undef TFR2
#undef INJ2
            const uint32_t bitsA = a0 ^ a1;   // partitionable 32-bit path
            const uint32_t bitsB = b0 ^ b1;

            // refresh threshold from the live block-shared best (value word)
            {
                unsigned sb;
                asm volatile("ld.shared.b32 %0, [%1+4];" : "=r"(sb) : "r"(pk_sa));
                if (sb > last_sb) { last_sb = sb; bthr = thr_from_mapped(sb, R); }
            }

            const bool pa = (bitsA >= bthr);
            const bool pb = (bitsB >= bthr);
            if (__any_sync(0xffffffffu, pa || pb)) {
                const int kA = tid + j * 512;
                unsigned long long cand = 0ull;
                if (pa) {
                    // uniform(tiny,1): f = bitcast((bits>>9)|0x3f800000)-1 ;
                    // u = max(tiny, f*(1-tiny)+tiny), (1-tiny)==1.0f exactly
                    const float f = __uint_as_float((bitsA >> 9) | 0x3f800000u) - 1.0f;
                    const float u = fmaxf(TINY32, f + TINY32);
                    const float g = -logf(-logf(u));    // libdevice logf (XLA-GPU)
                    const float v = g + __ldg(row + kA);
                    cand = ((unsigned long long)map_float(v) << 32) |
                           (unsigned)(0x7FFFFFFF - kA);
                }
                if (pb) {
                    const float f = __uint_as_float((bitsB >> 9) | 0x3f800000u) - 1.0f;
                    const float u = fmaxf(TINY32, f + TINY32);
                    const float g = -logf(-logf(u));
                    const float v = g + __ldg(row + kA + 256);
                    const unsigned long long c2 =
                        ((unsigned long long)map_float(v) << 32) |
                        (unsigned)(0x7FFFFFFF - (kA + 256));
                    if (c2 > cand) cand = c2;           // tie -> cand (lower k)
                }
                // u64 butterfly max: every lane ends with the warp max
                for (int o = 16; o > 0; o >>= 1) {
                    const unsigned long long oc =
                        __shfl_xor_sync(0xffffffffu, cand, o);
                    if (oc > cand) cand = oc;
                }
                if ((tid & 31) == 0 && cand != 0ull)
                    atomicMax(pk, cand);
                const unsigned sb2 = (unsigned)(cand >> 32);
                if (sb2 > last_sb) { last_sb = sb2; bthr = thr_from_mapped(sb2, R); }
            }
        }

        __syncthreads();                     // all atomicMax done; pack final
        const unsigned long long fp = *pk;   // ordered-after-barrier plain read
        prev = 0x7FFFFFFF - (int)(unsigned)(fp & 0xFFFFFFFFull);
        if (tid == 0) {
            out[(size_t)n * SLEN + s] = (float)prev;    // harness dtype: f32
            s_pack[(s + 2) % 3] = 0ull;      // distance-2 reuse: race-free
        }
    }
}

// ---------------------------------------------------------------------------
extern "C" void kernel_launch(void* const* d_in, const int* in_sizes, int n_in,
                              void* d_out, int out_size)
{
    const float* init_p  = (const float*)d_in[0];
    const float* trans_p = (const float*)d_in[1];
    float*       out     = (float*)d_out;

    // key = jax.random.key(42) -> threefry key (0, 42); partitionable split:
    // child i = full output pair of tf(master, (0, i))
    uint32_t a0, a1, b0, b1;
    threefry2x32(0u, 42u, 0u, 0u, &a0, &a1);   // k0    (first-state categorical)
    threefry2x32(0u, 42u, 0u, 1u, &b0, &b1);   // kloop (fold_in base)

    reset_kernel<<<1, 1>>>();
    prep_kernel<<<4096, 256>>>(init_p, trans_p, a0, a1, b0, b1);
    sample_kernel<<<NSEQ, 256>>>(out, 1u);
}

// round 11
// speedup vs baseline: 1.6527x; 1.6527x over previous
#include <cuda_runtime.h>
#include <stdint.h>
#include <math.h>

// Problem constants (fixed by the dataset problem)
#define KST   4096   // number of states
#define NSEQ  8192   // number of sequences
#define SLEN  1024   // sequence length

// Scratch (allocation-free rule: __device__ globals)
__device__ float g_log_init[KST];
__device__ float g_log_trans[(size_t)KST * KST];   // 64 MB, L2-resident
__device__ uint2 g_step_keys[SLEN];
__device__ float g_partial[4096];                  // per-prep-block max log

// ---------------------------------------------------------------------------
// Threefry-2x32 (20 rounds) — host/prep version
// ---------------------------------------------------------------------------
__host__ __device__ __forceinline__ uint32_t rotl32(uint32_t x, int r) {
#ifdef __CUDA_ARCH__
    return __funnelshift_l(x, x, r);
#else
    return (x << r) | (x >> (32 - r));
#endif
}

__host__ __device__ __forceinline__ void threefry2x32(
    uint32_t k0, uint32_t k1, uint32_t x0, uint32_t x1,
    uint32_t* o0, uint32_t* o1)
{
    const uint32_t k2 = k0 ^ k1 ^ 0x1BD11BDAu;
    x0 += k0; x1 += k1;
#define TF_R(r) { x0 += x1; x1 = rotl32(x1, (r)); x1 ^= x0; }
    TF_R(13) TF_R(15) TF_R(26) TF_R(6)
    x0 += k1; x1 += k2 + 1u;
    TF_R(17) TF_R(29) TF_R(16) TF_R(24)
    x0 += k2; x1 += k0 + 2u;
    TF_R(13) TF_R(15) TF_R(26) TF_R(6)
    x0 += k0; x1 += k1 + 3u;
    TF_R(17) TF_R(29) TF_R(16) TF_R(24)
    x0 += k1; x1 += k2 + 4u;
    TF_R(13) TF_R(15) TF_R(26) TF_R(6)
    x0 += k2; x1 += k0 + 5u;
#undef TF_R
    *o0 = x0; *o1 = x1;
}

// ---------------------------------------------------------------------------
// Prep: logs, step keys, per-block max into g_partial (plain deterministic
// stores — no reset kernel, no atomics needed).
// ---------------------------------------------------------------------------
__global__ void prep_kernel(const float* __restrict__ init_p,
                            const float* __restrict__ trans_p,
                            uint32_t key0x, uint32_t key0y,
                            uint32_t kloopx, uint32_t kloopy)
{
    __shared__ float sred[256];
    const long long idx    = (long long)blockIdx.x * blockDim.x + threadIdx.x;
    const long long stride = (long long)gridDim.x * blockDim.x;
    const long long total  = (long long)KST * KST;

    float lmax = -INFINITY;
    for (long long i = idx; i < total; i += stride) {
        const float l = logf(trans_p[i]);
        g_log_trans[i] = l;
        lmax = fmaxf(lmax, l);
    }
    if (idx < KST) {
        const float l = logf(init_p[idx]);
        g_log_init[idx] = l;
        lmax = fmaxf(lmax, l);
    }
    if (idx < SLEN) {
        if (idx == 0) {
            g_step_keys[0] = make_uint2(key0x, key0y);
        } else {
            uint32_t o0, o1;
            threefry2x32(kloopx, kloopy, 0u, (uint32_t)idx, &o0, &o1);
            g_step_keys[idx] = make_uint2(o0, o1);
        }
    }
    sred[threadIdx.x] = lmax;
    __syncthreads();
    for (int o = 128; o > 0; o >>= 1) {
        if (threadIdx.x < o)
            sred[threadIdx.x] = fmaxf(sred[threadIdx.x], sred[threadIdx.x + o]);
        __syncthreads();
    }
    if (threadIdx.x == 0)
        g_partial[blockIdx.x] = sred[0];
}

// ---------------------------------------------------------------------------
// Conservative bits-threshold from a mapped achieved best value.
// u_thr = exp(-exp(-(vb - R))), heavily under-padded so every skipped
// element is PROVABLY strictly below vb -> argmax unchanged bit-for-bit.
// ---------------------------------------------------------------------------
__device__ __forceinline__ uint32_t thr_from_mapped(unsigned m, float R)
{
    const unsigned ub = (m & 0x80000000u) ? (m & 0x7FFFFFFFu) : ~m;  // unmap
    const float vb = __uint_as_float(ub);
    const float t  = vb - R;
    const float w  = expf(-t);
    const float up = expf(-w) * 0.99998f;                  // >=10x composed err
    uint32_t nt = 0u;
    if (up >= 1.0f) {
        nt = 0xFFFFFFFFu;
    } else if (up > 0.0f) {
        const unsigned mant = __float_as_uint(1.0f + up) & 0x7FFFFFu;
        nt = (mant > 8u) ? ((mant - 8u) << 9) : 0u;        // extra ulp pad
    }
    return nt;   // NaN / nonpositive -> 0 (compute everything)
}

// ---------------------------------------------------------------------------
// Main sampler (R8 structure — best known — plus a REDUX batch gate).
//  - All-SHF threefry; adds on the FMA pipe (IMAD via runtime `one`).
//  - Per-batch gate: wmax = __reduce_max_sync(bits); uniform compare vs bthr
//    replaces per-element ISETP + VOTE on the binding ALU pipe. Gate passes
//    iff some element passes -> selection identical, output bit-exact.
//  - BLOCK-shared prune threshold + argmax in ONE shared 64-bit word:
//      pack = (mapped_value << 32) | (0x7FFFFFFF - index)
//    atomicMax (value-major; ties -> smaller index == XLA first-max).
//  - ONE __syncthreads per step (3-buffer rotation for race-free reset).
// Output written as float32 (harness output dtype).
// ---------------------------------------------------------------------------
__global__ void __launch_bounds__(256)
sample_kernel(float* __restrict__ out, uint32_t one)
{
    const int n    = blockIdx.x;
    const int tid  = threadIdx.x;

    __shared__ unsigned long long s_pack[3];
    __shared__ float s_red[256];

    // R = global max log, reduced from prep's per-block partials
    {
        float pm = -INFINITY;
#pragma unroll
        for (int i = 0; i < 4096 / 256; ++i)
            pm = fmaxf(pm, g_partial[tid + i * 256]);
        s_red[tid] = pm;
        __syncthreads();
        for (int o = 128; o > 0; o >>= 1) {
            if (tid < o) s_red[tid] = fmaxf(s_red[tid], s_red[tid + o]);
            __syncthreads();
        }
    }
    const float R = s_red[0];
    if (tid == 0) { s_pack[0] = 0ull; s_pack[1] = 0ull; s_pack[2] = 0ull; }
    __syncthreads();

    const uint32_t ebase  = (uint32_t)n * (uint32_t)KST;
    const float    TINY32 = 1.17549435e-38f;            // finfo(f32).tiny

    int prev = 0;  // unused at s=0 (uses log_init)

    for (int s = 0; s < SLEN; ++s) {
        const uint2 key = g_step_keys[s];
        const float* __restrict__ row =
            (s == 0) ? g_log_init : (g_log_trans + (size_t)prev * KST);

        const int bsel = s - (s / 3) * 3;               // s % 3
        unsigned long long* pk = &s_pack[bsel];
        const uint32_t pk_sa = (uint32_t)__cvta_generic_to_shared(pk);

        // hoisted key-injection constants
        const uint32_t k0 = key.x, k1 = key.y, kx = k0 ^ k1 ^ 0x1BD11BDAu;
        const uint32_t i1b = kx + 1u, i2b = k0 + 2u, i3b = k1 + 3u,
                       i4b = kx + 4u, i5b = k0 + 5u;
        const uint32_t x1base = k1 + ebase + (uint32_t)tid;

        unsigned last_sb = 0u;   // cached block-best (mapped); 0 < any real
        uint32_t bthr    = 0u;   // candidate iff bits >= bthr

#pragma unroll 4
        for (int j = 0; j < KST / 256; ++j) {
            // threefry(key, (hi=0, lo=ebase + tid + j*256)); x0 starts at k0
            uint32_t x0 = k0;
            uint32_t x1 = one * (uint32_t)(j * 256) + x1base;
#define TFR(r) { x0 = one * x0 + x1; x1 = __funnelshift_l(x1, x1, (r)) ^ x0; }
            TFR(13) TFR(15) TFR(26) TFR(6)
            x0 = one * x0 + k1; x1 = one * x1 + i1b;
            TFR(17) TFR(29) TFR(16) TFR(24)
            x0 = one * x0 + kx; x1 = one * x1 + i2b;
            TFR(13) TFR(15) TFR(26) TFR(6)
            x0 = one * x0 + k0; x1 = one * x1 + i3b;
            TFR(17) TFR(29) TFR(16) TFR(24)
            x0 = one * x0 + k1; x1 = one * x1 + i4b;
            TFR(13) TFR(15) TFR(26) TFR(6)
            x0 = one * x0 + kx; x1 = one * x1 + i5b;
#undef TFR
            const uint32_t bits = x0 ^ x1;   // partitionable 32-bit path

            // refresh threshold from the live block-shared best (value word)
            {
                unsigned sb;
                asm volatile("ld.shared.b32 %0, [%1+4];" : "=r"(sb) : "r"(pk_sa));
                if (sb > last_sb) { last_sb = sb; bthr = thr_from_mapped(sb, R); }
            }

            // batch gate: uniform branch, passes iff any element passes
            const uint32_t wmax = __reduce_max_sync(0xffffffffu, bits);
            if (wmax >= bthr) {
                const bool pass = (bits >= bthr);
                unsigned mk = 0u;
                if (pass) {
                    // uniform(tiny,1): f = bitcast((bits>>9)|0x3f800000)-1 ;
                    // u = max(tiny, f*(1-tiny)+tiny), (1-tiny)==1.0f exactly
                    const float f = __uint_as_float((bits >> 9) | 0x3f800000u) - 1.0f;
                    const float u = fmaxf(TINY32, f + TINY32);
                    const float g = -logf(-logf(u));    // libdevice logf (XLA-GPU)
                    const float v = g + __ldg(row + (tid + j * 256));
                    const unsigned ub = __float_as_uint(v);
                    mk = (ub & 0x80000000u) ? ~ub : (ub | 0x80000000u);  // order-map
                }
                const unsigned wm = __reduce_max_sync(0xffffffffu, mk);
                if (wm >= last_sb && wm != 0u) {
                    const unsigned sel = __ballot_sync(0xffffffffu, mk == wm);
                    const int src = __ffs(sel) - 1;     // lowest lane = lowest k
                    const int idx = (tid & ~31) + src + j * 256;
                    const unsigned long long cand =
                        ((unsigned long long)wm << 32) |
                        (unsigned)(0x7FFFFFFF - idx);
                    atomicMax(pk, cand);
                    last_sb = wm;
                    bthr = thr_from_mapped(wm, R);
                }
            }
        }

        __syncthreads();                     // all atomicMax done; pack final
        const unsigned long long fp = *pk;   // ordered-after-barrier plain read
        prev = 0x7FFFFFFF - (int)(unsigned)(fp & 0xFFFFFFFFull);
        if (tid == 0) {
            out[(size_t)n * SLEN + s] = (float)prev;    // harness dtype: f32
            s_pack[(s + 2) % 3] = 0ull;      // distance-2 reuse: race-free
        }
    }
}

// ---------------------------------------------------------------------------
extern "C" void kernel_launch(void* const* d_in, const int* in_sizes, int n_in,
                              void* d_out, int out_size)
{
    const float* init_p  = (const float*)d_in[0];
    const float* trans_p = (const float*)d_in[1];
    float*       out     = (float*)d_out;

    // key = jax.random.key(42) -> threefry key (0, 42); partitionable split:
    // child i = full output pair of tf(master, (0, i))
    uint32_t a0, a1, b0, b1;
    threefry2x32(0u, 42u, 0u, 0u, &a0, &a1);   // k0    (first-state categorical)
    threefry2x32(0u, 42u, 0u, 1u, &b0, &b1);   // kloop (fold_in base)

    prep_kernel<<<4096, 256>>>(init_p, trans_p, a0, a1, b0, b1);
    sample_kernel<<<NSEQ, 256>>>(out, 1u);
}